// round 3
// baseline (speedup 1.0000x reference)
#include <cuda_runtime.h>
#include <cuda_fp16.h>
#include <stdint.h>

// ============================ problem constants ============================
#define BATCHSZ 256
#define SEQLEN  512
#define EMBD    100
#define HIDDEN  1024
#define GATES   4096       // 4*HIDDEN, column-interleaved i,f,o,c per hidden unit
#define KTOT    1152       // HIDDEN + KX
#define KX      128        // padded embedding (100 -> 128, zero pad)
#define NCTA    128        // 2 M-tiles x 64 N-tiles
#define NTHR    256

// padded smem strides (halfs) -> conflict-free ldmatrix
#define SA 136             // A row stride: 272B, 16B-aligned, bank step 4
#define SB 1160            // B row stride: 2320B, 16B-aligned, bank step 4

// ============================ smem layout (bytes) =========================
#define S_BIAS  0u                       // 64 floats
#define S_A0    1024u                    // A chunk buf0: 128*136*2 = 34816
#define S_A1    (1024u + 34816u)         // A chunk buf1
#define S_B     (1024u + 69632u)         // resident B tile: 64*1160*2 = 148480
#define S_TOTAL (S_B + 148480u)          // 219136 bytes

// ============================ device scratch ==============================
__device__ __half g_WT[(size_t)GATES * KTOT];            // W^T [4096][1152] fp16
__device__ float  g_bperm[GATES];                        // permuted bias
__device__ __half g_X[(size_t)SEQLEN * BATCHSZ * KX];    // embedded tokens, padded
__device__ __half g_Hbuf[2][(size_t)BATCHSZ * HIDDEN];   // double-buffered H (fp16)
__device__ float  g_Hfinal[(size_t)BATCHSZ * HIDDEN];    // final H fp32
__device__ unsigned g_barrier;                           // grid barrier counter

// ============================ PTX helpers =================================
__device__ __forceinline__ uint32_t smem_u32(const void* p) {
    return (uint32_t)__cvta_generic_to_shared(p);
}

__device__ __forceinline__ void ldsm_x4(uint32_t addr, uint32_t& r0, uint32_t& r1,
                                        uint32_t& r2, uint32_t& r3) {
    asm volatile("ldmatrix.sync.aligned.m8n8.x4.shared.b16 {%0,%1,%2,%3}, [%4];"
                 : "=r"(r0), "=r"(r1), "=r"(r2), "=r"(r3) : "r"(addr));
}

__device__ __forceinline__ void mma16816(float* c,
                                         uint32_t a0, uint32_t a1, uint32_t a2, uint32_t a3,
                                         uint32_t b0, uint32_t b1) {
    asm volatile("mma.sync.aligned.m16n8k16.row.col.f32.f16.f16.f32 "
                 "{%0,%1,%2,%3}, {%4,%5,%6,%7}, {%8,%9}, {%0,%1,%2,%3};"
                 : "+f"(c[0]), "+f"(c[1]), "+f"(c[2]), "+f"(c[3])
                 : "r"(a0), "r"(a1), "r"(a2), "r"(a3), "r"(b0), "r"(b1));
}

__device__ __forceinline__ float tanh_fast(float x) {
    float y;
    asm("tanh.approx.f32 %0, %1;" : "=f"(y) : "f"(x));
    return y;
}

#define CP_ASYNC16(dst_u32, src_ptr) \
    asm volatile("cp.async.cg.shared.global [%0], [%1], 16;" \
                 :: "r"(dst_u32), "l"(src_ptr) : "memory")
#define CP_COMMIT asm volatile("cp.async.commit_group;" ::: "memory")
#define CP_WAIT0  asm volatile("cp.async.wait_group 0;"  ::: "memory")

// ============================ prep kernels ================================
__global__ void prep_pack(
    const float* __restrict__ Whi, const float* __restrict__ Whf,
    const float* __restrict__ Who, const float* __restrict__ Whc,
    const float* __restrict__ Wxi, const float* __restrict__ Wxf,
    const float* __restrict__ Wxo, const float* __restrict__ Wxc,
    const float* __restrict__ bi,  const float* __restrict__ bf,
    const float* __restrict__ bo,  const float* __restrict__ bc,
    const float* __restrict__ H0)
{
    size_t idx = (size_t)blockIdx.x * blockDim.x + threadIdx.x;
    if (idx < (size_t)GATES * KTOT) {
        int n = (int)(idx / KTOT);
        int k = (int)(idx % KTOT);
        int j = n >> 2, g = n & 3;
        float v = 0.f;
        if (k < HIDDEN) {
            const float* W = (g == 0) ? Whi : (g == 1) ? Whf : (g == 2) ? Who : Whc;
            v = W[(size_t)k * HIDDEN + j];
        } else if (k < HIDDEN + EMBD) {
            const float* W = (g == 0) ? Wxi : (g == 1) ? Wxf : (g == 2) ? Wxo : Wxc;
            v = W[(size_t)(k - HIDDEN) * HIDDEN + j];
        }
        g_WT[idx] = __float2half(v);
    }
    if (idx < GATES) {
        int j = (int)(idx >> 2), g = (int)(idx & 3);
        const float* bb = (g == 0) ? bi : (g == 1) ? bf : (g == 2) ? bo : bc;
        g_bperm[idx] = bb[j];
    }
    if (idx < (size_t)BATCHSZ * HIDDEN) g_Hbuf[0][idx] = __float2half(H0[idx]);
    if (idx == 0) g_barrier = 0u;
}

__global__ void prep_embed(const int* __restrict__ tokens, const float* __restrict__ emb)
{
    size_t idx = (size_t)blockIdx.x * blockDim.x + threadIdx.x;
    if (idx >= (size_t)SEQLEN * BATCHSZ * KX) return;
    int t = (int)(idx >> 15);          // BATCHSZ*KX = 32768
    int r = (int)((idx >> 7) & 255);
    int k = (int)(idx & 127);
    float v = 0.f;
    if (k < EMBD) {
        int tok = tokens[(size_t)r * SEQLEN + t];   // tokens[B,S]
        v = emb[(size_t)tok * EMBD + k];
    }
    g_X[idx] = __float2half(v);
}

// ============================ final dense =================================
__global__ void dense_out(const float* __restrict__ dw, const float* __restrict__ db,
                          float* __restrict__ out)
{
    int w    = (int)((blockIdx.x * blockDim.x + threadIdx.x) >> 5);
    int lane = threadIdx.x & 31;
    if (w >= BATCHSZ) return;
    const float* h = g_Hfinal + (size_t)w * HIDDEN;
    float s0 = 0.f, s1 = 0.f;
    for (int j = lane; j < HIDDEN; j += 32) {
        float x = h[j];
        s0 = fmaf(x, dw[j * 2 + 0], s0);
        s1 = fmaf(x, dw[j * 2 + 1], s1);
    }
#pragma unroll
    for (int o = 16; o; o >>= 1) {
        s0 += __shfl_xor_sync(0xffffffffu, s0, o);
        s1 += __shfl_xor_sync(0xffffffffu, s1, o);
    }
    if (lane == 0) {
        out[w * 2 + 0] = s0 + db[0];
        out[w * 2 + 1] = s1 + db[1];
    }
}

// ============================ main persistent LSTM ========================
__device__ __forceinline__ void load_chunk(uint32_t sdst, const __half* src, int ldh,
                                           int mt, int tid)
{
#pragma unroll
    for (int i = 0; i < 8; ++i) {
        int idx = tid + i * NTHR;
        int row = idx >> 4;
        int kc  = idx & 15;
        CP_ASYNC16(sdst + (uint32_t)(row * SA + kc * 8) * 2,
                   src + (size_t)(mt * 128 + row) * ldh + kc * 8);
    }
}

__global__ void __launch_bounds__(NTHR, 1) lstm_main(const float* __restrict__ C0)
{
    extern __shared__ __align__(16) char smem[];
    const uint32_t sb = smem_u32(smem);
    const int tid  = threadIdx.x;
    const int wid  = tid >> 5;
    const int lane = tid & 31;
    const int cta  = blockIdx.x;
    const int mt   = cta >> 6;   // 0..1  (batch-row tile)
    const int nt   = cta & 63;   // 0..63 (gate-col tile / 16 hidden units)

    const int wm = wid >> 1;     // 0..3 : M rows [wm*32, +32)
    const int wn = wid & 1;      // 0..1 : N cols [wn*32, +32)
    const int m0 = wm * 32;
    const int n0 = wn * 32;
    const int q  = lane & 1;     // 0: holds (i,f) gates; 1: holds (o,c)

    // ---- fill resident B tile + bias ----
    for (int i = tid; i < 64 * 144; i += NTHR) {
        int row = i / 144;
        int kc  = i % 144;
        uint4 v = *(const uint4*)(g_WT + (size_t)(nt * 64 + row) * KTOT + kc * 8);
        *(uint4*)(smem + S_B + (size_t)(row * SB + kc * 8) * 2) = v;
    }
    if (tid < 64) ((float*)(smem + S_BIAS))[tid] = g_bperm[nt * 64 + tid];
    __syncthreads();

    const float* bsm = (const float*)(smem + S_BIAS);
    float bb0[4], bb1[4];
    {
        int cb = wn * 32 + (lane & 3) * 2;
#pragma unroll
        for (int ni = 0; ni < 4; ++ni) {
            bb0[ni] = bsm[cb + ni * 8 + 0];
            bb1[ni] = bsm[cb + ni * 8 + 1];
        }
    }

    // ---- per-thread fragment addresses ----
    const uint32_t aoff0 = (uint32_t)(((m0 + (lane & 15)) * SA + (lane >> 4) * 8) * 2);
    const uint32_t aoff1 = aoff0 + 16u * SA * 2u;
    const uint32_t baddr0 = sb + S_B +
        (uint32_t)(((n0 + (lane & 7) + (lane >> 4) * 8) * SB + ((lane >> 3) & 1) * 8) * 2);
    const uint32_t baddr1 = baddr0 + 16u * SB * 2u;

    // ---- C state + unit/row indices ----
    const int rowq = mt * 128 + m0 + (lane >> 2);   // + mi*16 + cp*8
    int junit[4];
#pragma unroll
    for (int ni = 0; ni < 4; ++ni)
        junit[ni] = nt * 16 + wn * 8 + ni * 2 + ((lane & 3) >> 1);

    float Cst[16];
#pragma unroll
    for (int mi = 0; mi < 2; ++mi)
#pragma unroll
        for (int cp = 0; cp < 2; ++cp)
#pragma unroll
            for (int ni = 0; ni < 4; ++ni)
                Cst[(mi * 2 + cp) * 4 + ni] =
                    C0[(size_t)(rowq + mi * 16 + cp * 8) * HIDDEN + junit[ni]];

    // =============================== time loop ===============================
    for (int t = 0; t < SEQLEN; ++t) {
        const __half* Hsrc = g_Hbuf[t & 1];
        __half*       Hdst = g_Hbuf[(t & 1) ^ 1];

        float acc[2][4][4];
#pragma unroll
        for (int mi = 0; mi < 2; ++mi)
#pragma unroll
            for (int ni = 0; ni < 4; ++ni)
#pragma unroll
                for (int c = 0; c < 4; ++c) acc[mi][ni][c] = 0.f;

        // preload chunk 0
        load_chunk(sb + S_A0, Hsrc, HIDDEN, mt, tid);
        CP_COMMIT; CP_WAIT0;
        __syncthreads();

#pragma unroll 1
        for (int ch = 0; ch < 9; ++ch) {
            const uint32_t ab = sb + ((ch & 1) ? S_A1 : S_A0);
            if (ch < 8) {
                const uint32_t nb = sb + ((ch & 1) ? S_A0 : S_A1);
                if (ch < 7) load_chunk(nb, Hsrc + (ch + 1) * 128, HIDDEN, mt, tid);
                else        load_chunk(nb, g_X + (size_t)t * (BATCHSZ * KX), KX, mt, tid);
                CP_COMMIT;
            }
            // B advances by 128 k-columns (256 bytes) per chunk  <-- round-2 fix
            const uint32_t bk = (uint32_t)ch * 256u;
#pragma unroll
            for (int ks = 0; ks < 8; ++ks) {
                uint32_t a0[4], a1[4], b0[4], b1[4];
                ldsm_x4(ab + aoff0 + ks * 32, a0[0], a0[1], a0[2], a0[3]);
                ldsm_x4(ab + aoff1 + ks * 32, a1[0], a1[1], a1[2], a1[3]);
                ldsm_x4(baddr0 + bk + ks * 32, b0[0], b0[1], b0[2], b0[3]);
                ldsm_x4(baddr1 + bk + ks * 32, b1[0], b1[1], b1[2], b1[3]);
                mma16816(acc[0][0], a0[0], a0[1], a0[2], a0[3], b0[0], b0[1]);
                mma16816(acc[0][1], a0[0], a0[1], a0[2], a0[3], b0[2], b0[3]);
                mma16816(acc[0][2], a0[0], a0[1], a0[2], a0[3], b1[0], b1[1]);
                mma16816(acc[0][3], a0[0], a0[1], a0[2], a0[3], b1[2], b1[3]);
                mma16816(acc[1][0], a1[0], a1[1], a1[2], a1[3], b0[0], b0[1]);
                mma16816(acc[1][1], a1[0], a1[1], a1[2], a1[3], b0[2], b0[3]);
                mma16816(acc[1][2], a1[0], a1[1], a1[2], a1[3], b1[0], b1[1]);
                mma16816(acc[1][3], a1[0], a1[1], a1[2], a1[3], b1[2], b1[3]);
            }
            CP_WAIT0;
            __syncthreads();
        }

        // -------- epilogue: gates -> (C,H) via lane-pair exchange --------
#pragma unroll
        for (int mi = 0; mi < 2; ++mi)
#pragma unroll
            for (int cp = 0; cp < 2; ++cp)
#pragma unroll
                for (int ni = 0; ni < 4; ++ni) {
                    const int cidx = (mi * 2 + cp) * 4 + ni;
                    float g0 = acc[mi][ni][cp * 2 + 0] + bb0[ni];
                    float g1 = acc[mi][ni][cp * 2 + 1] + bb1[ni];
                    // even lane: v0=I=sig(gi), v1=F=sig(gf)
                    // odd  lane: v0=O=sig(go), v1=T=tanh(gc)
                    float v0 = 0.5f * tanh_fast(0.5f * g0) + 0.5f;
                    float t1 = tanh_fast(q ? g1 : 0.5f * g1);
                    float v1 = q ? t1 : (0.5f * t1 + 0.5f);
                    float Tx = __shfl_xor_sync(0xffffffffu, v1, 1); // even gets T
                    float Cn = v1 * Cst[cidx] + v0 * Tx;            // even: F*C + I*T
                    if (!q) Cst[cidx] = Cn;
                    float Th  = tanh_fast(Cn);                      // even: tanh(Cnew)
                    float Thx = __shfl_xor_sync(0xffffffffu, Th, 1);// odd gets tanh(Cnew)
                    if (q) {
                        float Hv = v0 * Thx;                        // O * tanh(Cnew)
                        size_t o = (size_t)(rowq + mi * 16 + cp * 8) * HIDDEN + junit[ni];
                        Hdst[o] = __float2half(Hv);
                        if (t == SEQLEN - 1) g_Hfinal[o] = Hv;
                    }
                }

        // -------- grid barrier (all 128 CTAs co-resident) --------
        __threadfence();
        __syncthreads();
        if (tid == 0) {
            unsigned target = (unsigned)(t + 1) * NCTA;
            atomicAdd(&g_barrier, 1u);
            while (*(volatile unsigned*)&g_barrier < target) { }
            __threadfence();
        }
        __syncthreads();
    }
}

// ============================ launch ======================================
extern "C" void kernel_launch(void* const* d_in, const int* in_sizes, int n_in,
                              void* d_out, int out_size)
{
    const int*   tokens = (const int*)  d_in[0];
    const float* H0     = (const float*)d_in[1];
    const float* C0     = (const float*)d_in[2];
    const float* W_xi   = (const float*)d_in[3];
    const float* W_hi   = (const float*)d_in[4];
    const float* b_i    = (const float*)d_in[5];
    const float* W_xf   = (const float*)d_in[6];
    const float* W_hf   = (const float*)d_in[7];
    const float* b_f    = (const float*)d_in[8];
    const float* W_xo   = (const float*)d_in[9];
    const float* W_ho   = (const float*)d_in[10];
    const float* b_o    = (const float*)d_in[11];
    const float* W_xc   = (const float*)d_in[12];
    const float* W_hc   = (const float*)d_in[13];
    const float* b_c    = (const float*)d_in[14];
    const float* emb    = (const float*)d_in[15];
    const float* dw     = (const float*)d_in[16];
    const float* db     = (const float*)d_in[17];
    float* out = (float*)d_out;

    cudaFuncSetAttribute(lstm_main, cudaFuncAttributeMaxDynamicSharedMemorySize, S_TOTAL);

    {
        size_t total = (size_t)GATES * KTOT;
        int blocks = (int)((total + 255) / 256);
        prep_pack<<<blocks, 256>>>(W_hi, W_hf, W_ho, W_hc,
                                   W_xi, W_xf, W_xo, W_xc,
                                   b_i, b_f, b_o, b_c, H0);
    }
    {
        size_t total = (size_t)SEQLEN * BATCHSZ * KX;
        int blocks = (int)((total + 255) / 256);
        prep_embed<<<blocks, 256>>>(tokens, emb);
    }
    lstm_main<<<NCTA, NTHR, S_TOTAL>>>(C0);
    dense_out<<<32, 256>>>(dw, db, out);
}

// round 4
// speedup vs baseline: 1.1410x; 1.1410x over previous
#include <cuda_runtime.h>
#include <cuda_fp16.h>
#include <stdint.h>

// ============================ problem constants ============================
#define BATCHSZ 256
#define SEQLEN  512
#define EMBD    100
#define HIDDEN  1024
#define GATES   4096       // 4*HIDDEN, column-interleaved i,f,o,c per hidden unit
#define KTOT    1152       // HIDDEN + KX
#define KX      128        // padded embedding (100 -> 128, zero pad)
#define NCTA    128        // 2 M-tiles x 64 N-tiles
#define NTHR    256

// padded smem strides (halfs) -> conflict-free ldmatrix
#define SA 136             // A row stride
#define SB 1160            // B row stride

// ============================ smem layout (bytes) =========================
#define S_BIAS  0u                       // 64 floats
#define S_A0    1024u                    // A chunk buf0: 128*136*2 = 34816
#define S_B     (1024u + 69632u)         // resident B tile: 64*1160*2 = 148480
#define S_TOTAL (S_B + 148480u)          // 219136 bytes

// ============================ device scratch ==============================
__device__ __half g_WT[(size_t)GATES * KTOT];            // W^T [4096][1152] fp16
__device__ float  g_bperm[GATES];                        // permuted bias
__device__ __half g_X[(size_t)SEQLEN * BATCHSZ * KX];    // embedded tokens, padded
__device__ __half g_Hbuf[2][(size_t)BATCHSZ * HIDDEN];   // double-buffered H (fp16)
__device__ float  g_Hfinal[(size_t)BATCHSZ * HIDDEN];    // final H fp32
__device__ __align__(128) unsigned g_bar2[64];           // [0]: mt=0, [32]: mt=1

// ============================ PTX helpers =================================
__device__ __forceinline__ uint32_t smem_u32(const void* p) {
    return (uint32_t)__cvta_generic_to_shared(p);
}

__device__ __forceinline__ void ldsm_x4(uint32_t addr, uint32_t& r0, uint32_t& r1,
                                        uint32_t& r2, uint32_t& r3) {
    asm volatile("ldmatrix.sync.aligned.m8n8.x4.shared.b16 {%0,%1,%2,%3}, [%4];"
                 : "=r"(r0), "=r"(r1), "=r"(r2), "=r"(r3) : "r"(addr));
}

__device__ __forceinline__ void mma16816(float* c,
                                         uint32_t a0, uint32_t a1, uint32_t a2, uint32_t a3,
                                         uint32_t b0, uint32_t b1) {
    asm volatile("mma.sync.aligned.m16n8k16.row.col.f32.f16.f16.f32 "
                 "{%0,%1,%2,%3}, {%4,%5,%6,%7}, {%8,%9}, {%0,%1,%2,%3};"
                 : "+f"(c[0]), "+f"(c[1]), "+f"(c[2]), "+f"(c[3])
                 : "r"(a0), "r"(a1), "r"(a2), "r"(a3), "r"(b0), "r"(b1));
}

__device__ __forceinline__ float tanh_fast(float x) {
    float y;
    asm("tanh.approx.f32 %0, %1;" : "=f"(y) : "f"(x));
    return y;
}

#define CP_ASYNC16(dst_u32, src_ptr) \
    asm volatile("cp.async.cg.shared.global [%0], [%1], 16;" \
                 :: "r"(dst_u32), "l"(src_ptr) : "memory")
#define CP_COMMIT asm volatile("cp.async.commit_group;" ::: "memory")
#define CP_WAIT0  asm volatile("cp.async.wait_group 0;"  ::: "memory")

// ============================ prep kernels ================================
__global__ void prep_pack(
    const float* __restrict__ Whi, const float* __restrict__ Whf,
    const float* __restrict__ Who, const float* __restrict__ Whc,
    const float* __restrict__ Wxi, const float* __restrict__ Wxf,
    const float* __restrict__ Wxo, const float* __restrict__ Wxc,
    const float* __restrict__ bi,  const float* __restrict__ bf,
    const float* __restrict__ bo,  const float* __restrict__ bc,
    const float* __restrict__ H0)
{
    size_t idx = (size_t)blockIdx.x * blockDim.x + threadIdx.x;
    if (idx < (size_t)GATES * KTOT) {
        int n = (int)(idx / KTOT);
        int k = (int)(idx % KTOT);
        int j = n >> 2, g = n & 3;
        float v = 0.f;
        if (k < HIDDEN) {
            const float* W = (g == 0) ? Whi : (g == 1) ? Whf : (g == 2) ? Who : Whc;
            v = W[(size_t)k * HIDDEN + j];
        } else if (k < HIDDEN + EMBD) {
            const float* W = (g == 0) ? Wxi : (g == 1) ? Wxf : (g == 2) ? Wxo : Wxc;
            v = W[(size_t)(k - HIDDEN) * HIDDEN + j];
        }
        g_WT[idx] = __float2half(v);
    }
    if (idx < GATES) {
        int j = (int)(idx >> 2), g = (int)(idx & 3);
        const float* bb = (g == 0) ? bi : (g == 1) ? bf : (g == 2) ? bo : bc;
        g_bperm[idx] = bb[j];
    }
    if (idx < (size_t)BATCHSZ * HIDDEN) g_Hbuf[0][idx] = __float2half(H0[idx]);
    if (idx < 64) g_bar2[idx] = 0u;
}

__global__ void prep_embed(const int* __restrict__ tokens, const float* __restrict__ emb)
{
    size_t idx = (size_t)blockIdx.x * blockDim.x + threadIdx.x;
    if (idx >= (size_t)SEQLEN * BATCHSZ * KX) return;
    int t = (int)(idx >> 15);          // BATCHSZ*KX = 32768
    int r = (int)((idx >> 7) & 255);
    int k = (int)(idx & 127);
    float v = 0.f;
    if (k < EMBD) {
        int tok = tokens[(size_t)r * SEQLEN + t];   // tokens[B,S]
        v = emb[(size_t)tok * EMBD + k];
    }
    g_X[idx] = __float2half(v);
}

// ============================ final dense =================================
__global__ void dense_out(const float* __restrict__ dw, const float* __restrict__ db,
                          float* __restrict__ out)
{
    int w    = (int)((blockIdx.x * blockDim.x + threadIdx.x) >> 5);
    int lane = threadIdx.x & 31;
    if (w >= BATCHSZ) return;
    const float* h = g_Hfinal + (size_t)w * HIDDEN;
    float s0 = 0.f, s1 = 0.f;
    for (int j = lane; j < HIDDEN; j += 32) {
        float x = h[j];
        s0 = fmaf(x, dw[j * 2 + 0], s0);
        s1 = fmaf(x, dw[j * 2 + 1], s1);
    }
#pragma unroll
    for (int o = 16; o; o >>= 1) {
        s0 += __shfl_xor_sync(0xffffffffu, s0, o);
        s1 += __shfl_xor_sync(0xffffffffu, s1, o);
    }
    if (lane == 0) {
        out[w * 2 + 0] = s0 + db[0];
        out[w * 2 + 1] = s1 + db[1];
    }
}

// ============================ main persistent LSTM ========================
__device__ __forceinline__ void load_chunk(uint32_t sdst, const __half* src, int ldh,
                                           int mt, int tid)
{
#pragma unroll
    for (int i = 0; i < 8; ++i) {
        int idx = tid + i * NTHR;
        int row = idx >> 4;
        int kc  = idx & 15;
        CP_ASYNC16(sdst + (uint32_t)(row * SA + kc * 8) * 2,
                   src + (size_t)(mt * 128 + row) * ldh + kc * 8);
    }
}

__global__ void __launch_bounds__(NTHR, 1) lstm_main(const float* __restrict__ C0)
{
    extern __shared__ __align__(16) char smem[];
    const uint32_t sb = smem_u32(smem);
    const int tid  = threadIdx.x;
    const int wid  = tid >> 5;
    const int lane = tid & 31;
    const int cta  = blockIdx.x;
    const int mt   = cta >> 6;   // 0..1  (batch-row tile)
    const int nt   = cta & 63;   // 0..63 (gate-col tile / 16 hidden units)

    const int wm = wid >> 1;     // 0..3 : M rows [wm*32, +32)
    const int wn = wid & 1;      // 0..1 : N cols [wn*32, +32)
    const int m0 = wm * 32;
    const int n0 = wn * 32;
    const int q  = lane & 1;     // 0: holds (i,f) gates; 1: holds (o,c)

    // ---- fill resident B tile + bias ----
    for (int i = tid; i < 64 * 144; i += NTHR) {
        int row = i / 144;
        int kc  = i % 144;
        uint4 v = *(const uint4*)(g_WT + (size_t)(nt * 64 + row) * KTOT + kc * 8);
        *(uint4*)(smem + S_B + (size_t)(row * SB + kc * 8) * 2) = v;
    }
    if (tid < 64) ((float*)(smem + S_BIAS))[tid] = g_bperm[nt * 64 + tid];

    // prefetch X(0) into buf 0 (chunk c=0, t=0 -> parity 0)
    load_chunk(sb + S_A0, g_X, KX, mt, tid);
    CP_COMMIT;
    __syncthreads();

    const float* bsm = (const float*)(smem + S_BIAS);
    float bb0[4], bb1[4];
    {
        int cb = wn * 32 + (lane & 3) * 2;
#pragma unroll
        for (int ni = 0; ni < 4; ++ni) {
            bb0[ni] = bsm[cb + ni * 8 + 0];
            bb1[ni] = bsm[cb + ni * 8 + 1];
        }
    }

    // ---- per-thread fragment addresses ----
    const uint32_t aoff0 = (uint32_t)(((m0 + (lane & 15)) * SA + (lane >> 4) * 8) * 2);
    const uint32_t aoff1 = aoff0 + 16u * SA * 2u;
    const uint32_t baddr0 = sb + S_B +
        (uint32_t)(((n0 + (lane & 7) + (lane >> 4) * 8) * SB + ((lane >> 3) & 1) * 8) * 2);
    const uint32_t baddr1 = baddr0 + 16u * SB * 2u;

    // ---- C state + unit/row indices ----
    const int rowq = mt * 128 + m0 + (lane >> 2);   // + mi*16 + cp*8
    const int colbase = nt * 16 + wn * 8;           // 8 contiguous units per (row)
    int junit[4];
#pragma unroll
    for (int ni = 0; ni < 4; ++ni)
        junit[ni] = colbase + ni * 2 + ((lane & 3) >> 1);

    float Cst[16];
#pragma unroll
    for (int mi = 0; mi < 2; ++mi)
#pragma unroll
        for (int cp = 0; cp < 2; ++cp)
#pragma unroll
            for (int ni = 0; ni < 4; ++ni)
                Cst[(mi * 2 + cp) * 4 + ni] =
                    C0[(size_t)(rowq + mi * 16 + cp * 8) * HIDDEN + junit[ni]];

    unsigned* const barctr = &g_bar2[mt * 32];

    // =============================== time loop ===============================
    for (int t = 0; t < SEQLEN; ++t) {
        const unsigned pt = (unsigned)t & 1u;
        const __half* Hsrc = g_Hbuf[t & 1];
        __half*       Hdst = g_Hbuf[(t & 1) ^ 1];

        // acc initialized with bias (folded)
        float acc[2][4][4];
#pragma unroll
        for (int mi = 0; mi < 2; ++mi)
#pragma unroll
            for (int ni = 0; ni < 4; ++ni) {
                acc[mi][ni][0] = bb0[ni]; acc[mi][ni][1] = bb1[ni];
                acc[mi][ni][2] = bb0[ni]; acc[mi][ni][3] = bb1[ni];
            }

        // X(t) prefetched into buf (t&1) already; wait + publish
        CP_WAIT0;
        __syncthreads();

        // chunk order: c=0 -> X(t) (k-block 8), c=1..8 -> H blocks 0..7
#pragma unroll 1
        for (int c = 0; c < 9; ++c) {
            const uint32_t ab = sb + S_A0 + ((((unsigned)c + pt) & 1u) ? 34816u : 0u);
            if (c < 8) {
                // prefetch chunk c+1 = H block c
                const uint32_t nb = sb + S_A0 + ((((unsigned)c + 1u + pt) & 1u) ? 34816u : 0u);
                load_chunk(nb, Hsrc + c * 128, HIDDEN, mt, tid);
                CP_COMMIT;
            } else if (t + 1 < SEQLEN) {
                // prefetch X(t+1) into buf ((t+1)&1): hides under epilogue+barrier
                const uint32_t nb = sb + S_A0 + ((pt ^ 1u) ? 34816u : 0u);
                load_chunk(nb, g_X + (size_t)(t + 1) * (BATCHSZ * KX), KX, mt, tid);
                CP_COMMIT;
            }
            const uint32_t bk = (c == 0) ? 8u * 256u : (uint32_t)(c - 1) * 256u;
#pragma unroll
            for (int ks = 0; ks < 8; ++ks) {
                uint32_t a0[4], a1[4], b0[4], b1[4];
                ldsm_x4(ab + aoff0 + ks * 32, a0[0], a0[1], a0[2], a0[3]);
                ldsm_x4(ab + aoff1 + ks * 32, a1[0], a1[1], a1[2], a1[3]);
                ldsm_x4(baddr0 + bk + ks * 32, b0[0], b0[1], b0[2], b0[3]);
                ldsm_x4(baddr1 + bk + ks * 32, b1[0], b1[1], b1[2], b1[3]);
                mma16816(acc[0][0], a0[0], a0[1], a0[2], a0[3], b0[0], b0[1]);
                mma16816(acc[0][1], a0[0], a0[1], a0[2], a0[3], b0[2], b0[3]);
                mma16816(acc[0][2], a0[0], a0[1], a0[2], a0[3], b1[0], b1[1]);
                mma16816(acc[0][3], a0[0], a0[1], a0[2], a0[3], b1[2], b1[3]);
                mma16816(acc[1][0], a1[0], a1[1], a1[2], a1[3], b0[0], b0[1]);
                mma16816(acc[1][1], a1[0], a1[1], a1[2], a1[3], b0[2], b0[3]);
                mma16816(acc[1][2], a1[0], a1[1], a1[2], a1[3], b1[0], b1[1]);
                mma16816(acc[1][3], a1[0], a1[1], a1[2], a1[3], b1[2], b1[3]);
            }
            if (c < 8) { CP_WAIT0; __syncthreads(); }
        }

        // -------- epilogue: gates -> (C,H); packed 16B H stores --------
#pragma unroll
        for (int mi = 0; mi < 2; ++mi)
#pragma unroll
            for (int cp = 0; cp < 2; ++cp) {
                uint32_t h2[4];
                float hv_f[4], hp_f[4];
#pragma unroll
                for (int ni = 0; ni < 4; ++ni) {
                    const int cidx = (mi * 2 + cp) * 4 + ni;
                    float g0 = acc[mi][ni][cp * 2 + 0];
                    float g1 = acc[mi][ni][cp * 2 + 1];
                    // even lane: v0=I=sig(gi), v1=F=sig(gf)
                    // odd  lane: v0=O=sig(go), v1=T=tanh(gc)
                    float v0 = 0.5f * tanh_fast(0.5f * g0) + 0.5f;
                    float t1 = tanh_fast(q ? g1 : 0.5f * g1);
                    float v1 = q ? t1 : (0.5f * t1 + 0.5f);
                    float Tx = __shfl_xor_sync(0xffffffffu, v1, 1); // even gets T
                    float Cn = v1 * Cst[cidx] + v0 * Tx;            // even: F*C + I*T
                    if (!q) Cst[cidx] = Cn;
                    float Th  = tanh_fast(Cn);                      // even: tanh(Cnew)
                    float Thx = __shfl_xor_sync(0xffffffffu, Th, 1);// odd gets tanh(Cnew)
                    float Hv  = v0 * Thx;                           // odd: O*tanh(Cnew)
                    float Hp  = __shfl_xor_sync(0xffffffffu, Hv, 2);// lane&3==1 gets lane&3==3
                    __half2 p = __halves2half2(__float2half(Hv), __float2half(Hp));
                    h2[ni] = *(uint32_t*)&p;
                    hv_f[ni] = Hv; hp_f[ni] = Hp;
                }
                if ((lane & 3) == 1) {
                    const int row = rowq + mi * 16 + cp * 8;
                    *(uint4*)(Hdst + (size_t)row * HIDDEN + colbase) =
                        make_uint4(h2[0], h2[1], h2[2], h2[3]);
                    if (t == SEQLEN - 1) {
                        float* fp = g_Hfinal + (size_t)row * HIDDEN + colbase;
                        *(float4*)(fp)     = make_float4(hv_f[0], hp_f[0], hv_f[1], hp_f[1]);
                        *(float4*)(fp + 4) = make_float4(hv_f[2], hp_f[2], hv_f[3], hp_f[3]);
                    }
                }
            }

        // -------- split grid barrier: 64 CTAs per mt group --------
        __syncthreads();
        if (tid == 0) {
            __threadfence();
            asm volatile("red.release.gpu.global.add.u32 [%0], 1;"
                         :: "l"(barctr) : "memory");
            const unsigned target = (unsigned)(t + 1) * 64u;
            unsigned v;
            do {
                asm volatile("ld.acquire.gpu.global.u32 %0, [%1];"
                             : "=r"(v) : "l"(barctr) : "memory");
            } while (v < target);
        }
        __syncthreads();
    }
}

// ============================ launch ======================================
extern "C" void kernel_launch(void* const* d_in, const int* in_sizes, int n_in,
                              void* d_out, int out_size)
{
    const int*   tokens = (const int*)  d_in[0];
    const float* H0     = (const float*)d_in[1];
    const float* C0     = (const float*)d_in[2];
    const float* W_xi   = (const float*)d_in[3];
    const float* W_hi   = (const float*)d_in[4];
    const float* b_i    = (const float*)d_in[5];
    const float* W_xf   = (const float*)d_in[6];
    const float* W_hf   = (const float*)d_in[7];
    const float* b_f    = (const float*)d_in[8];
    const float* W_xo   = (const float*)d_in[9];
    const float* W_ho   = (const float*)d_in[10];
    const float* b_o    = (const float*)d_in[11];
    const float* W_xc   = (const float*)d_in[12];
    const float* W_hc   = (const float*)d_in[13];
    const float* b_c    = (const float*)d_in[14];
    const float* emb    = (const float*)d_in[15];
    const float* dw     = (const float*)d_in[16];
    const float* db     = (const float*)d_in[17];
    float* out = (float*)d_out;

    cudaFuncSetAttribute(lstm_main, cudaFuncAttributeMaxDynamicSharedMemorySize, S_TOTAL);

    {
        size_t total = (size_t)GATES * KTOT;
        int blocks = (int)((total + 255) / 256);
        prep_pack<<<blocks, 256>>>(W_hi, W_hf, W_ho, W_hc,
                                   W_xi, W_xf, W_xo, W_xc,
                                   b_i, b_f, b_o, b_c, H0);
    }
    {
        size_t total = (size_t)SEQLEN * BATCHSZ * KX;
        int blocks = (int)((total + 255) / 256);
        prep_embed<<<blocks, 256>>>(tokens, emb);
    }
    lstm_main<<<NCTA, NTHR, S_TOTAL>>>(C0);
    dense_out<<<32, 256>>>(dw, db, out);
}